// round 13
// baseline (speedup 1.0000x reference)
#include <cuda_runtime.h>
#include <cuda_fp16.h>
#include <math.h>
#include <stdint.h>

// ---------------- problem constants ----------------
#define B_      8
#define Hh      64
#define Ww      64
#define Cc      384
#define HEADS   12
#define WSs     14
#define KD      32
#define Nt      196
#define NW      200
#define M_ATT   39200
#define L_      4096
#define M_MLP   32768
#define HID     1536
#define DH      384
#define QKVW    1152
#define SCALE_F 0.17677669529663687f
#define EPS_F   1e-5f

// attention tiling
#define NTP        208
#define AQ_STR     40
#define SMEM_ATTN  (3 * NTP * AQ_STR * 2)

// fp16 gemm smem: 3 stages x (A[128][40] + B[128][40]) halfs
#define GST_BYTES   20480
#define SMEM_GEMM   (3 * GST_BYTES)

// ---------------- scratch ----------------
__device__ __align__(16) __half g_xn[M_ATT * Cc];
__device__ __align__(16) __half g_qkv[(size_t)M_ATT * QKVW];
__device__ __align__(16) __half g_attno[M_ATT * Cc];
__device__ float  g_x1[M_MLP * Cc];
__device__ float  g_x2[M_MLP * Cc];
__device__ __align__(16) __half g_h1[(size_t)M_MLP * HID];
__device__ float  g_bias[HEADS * Nt * Nt];
__device__ __align__(16) __half g_wq[QKVW * Cc];
__device__ __align__(16) __half g_wp[Cc * DH];
__device__ __align__(16) __half g_w1[HID * Cc];
__device__ __align__(16) __half g_w2[Cc * HID];

// ---------------- helpers ----------------
__device__ __forceinline__ void mma_f16(float* c, const uint32_t* a, const uint32_t* b) {
    asm volatile(
        "mma.sync.aligned.m16n8k16.row.col.f32.f16.f16.f32 "
        "{%0,%1,%2,%3}, {%4,%5,%6,%7}, {%8,%9}, {%0,%1,%2,%3};\n"
        : "+f"(c[0]), "+f"(c[1]), "+f"(c[2]), "+f"(c[3])
        : "r"(a[0]), "r"(a[1]), "r"(a[2]), "r"(a[3]), "r"(b[0]), "r"(b[1]));
}

__device__ __forceinline__ void ldsm_x4(uint32_t* r, uint32_t saddr) {
    asm volatile("ldmatrix.sync.aligned.m8n8.x4.shared.b16 {%0,%1,%2,%3}, [%4];"
                 : "=r"(r[0]), "=r"(r[1]), "=r"(r[2]), "=r"(r[3]) : "r"(saddr));
}

__device__ __forceinline__ void ldsm_x4_t(uint32_t* r, uint32_t saddr) {
    asm volatile("ldmatrix.sync.aligned.m8n8.x4.trans.shared.b16 {%0,%1,%2,%3}, [%4];"
                 : "=r"(r[0]), "=r"(r[1]), "=r"(r[2]), "=r"(r[3]) : "r"(saddr));
}

__device__ __forceinline__ void cp_async16(uint32_t saddr, const void* gptr, int srcbytes) {
    asm volatile("cp.async.cg.shared.global [%0], [%1], 16, %2;\n"
                 :: "r"(saddr), "l"(gptr), "r"(srcbytes));
}

__device__ __forceinline__ uint32_t smem_u32(const void* p) {
    uint32_t a;
    asm("{ .reg .u64 t; cvta.to.shared.u64 t, %1; cvt.u32.u64 %0, t; }" : "=r"(a) : "l"(p));
    return a;
}

__device__ __forceinline__ uint32_t h2u(__half2 h) {
    return *(uint32_t*)&h;
}

// ---------------- weight conversion fp32 -> fp16 ----------------
__global__ void k_half_all(const float4* __restrict__ s0, int n0,
                           const float4* __restrict__ s1, int n1,
                           const float4* __restrict__ s2, int n2,
                           const float4* __restrict__ s3, int n3) {
    int i = blockIdx.x * blockDim.x + threadIdx.x;
    const float4* src; __half* dst; int j = i;
    if (j < n0) { src = s0; dst = g_wq; }
    else if ((j -= n0) < n1) { src = s1; dst = g_wp; }
    else if ((j -= n1) < n2) { src = s2; dst = g_w1; }
    else if ((j -= n2) < n3) { src = s3; dst = g_w2; }
    else return;
    float4 v = src[j];
    __half2* d2 = (__half2*)(dst + 4 * (size_t)j);
    d2[0] = __floats2half2_rn(v.x, v.y);
    d2[1] = __floats2half2_rn(v.z, v.w);
}

// ---------------- kernel: expand bias table ----------------
__global__ void k_bias_expand(const float* __restrict__ ab,
                              const int* __restrict__ bidx, int n_off) {
    int i = blockIdx.x * blockDim.x + threadIdx.x;
    if (i >= HEADS * Nt * Nt) return;
    int h  = i / (Nt * Nt);
    int ij = i - h * (Nt * Nt);
    g_bias[i] = ab[h * n_off + bidx[ij]];
}

// ---------------- kernel: window partition + LayerNorm (fp16 out) ---------
__global__ void k_win_ln(const float* __restrict__ x,
                         const float* __restrict__ w,
                         const float* __restrict__ b) {
    int warp = (blockIdx.x * blockDim.x + threadIdx.x) >> 5;
    int lane = threadIdx.x & 31;
    if (warp >= M_ATT) return;
    int wi = warp / Nt, t = warp - wi * Nt;
    int bb = wi / 25; int rem = wi - bb * 25;
    int wy = rem / 5, wx = rem - wy * 5;
    int ty = t / WSs, tx = t - ty * WSs;
    int gy = wy * WSs + ty, gx = wx * WSs + tx;
    bool valid = (gy < Hh) && (gx < Ww);
    const float* src = x + ((size_t)bb * L_ + (size_t)gy * Ww + gx) * Cc;

    float vals[12];
    float s = 0.f, s2 = 0.f;
#pragma unroll
    for (int i = 0; i < 12; i++) {
        float v = valid ? src[lane + i * 32] : 0.f;
        vals[i] = v; s += v; s2 += v * v;
    }
#pragma unroll
    for (int o = 16; o > 0; o >>= 1) {
        s  += __shfl_xor_sync(0xffffffffu, s,  o);
        s2 += __shfl_xor_sync(0xffffffffu, s2, o);
    }
    float mean = s * (1.f / Cc);
    float var  = s2 * (1.f / Cc) - mean * mean;
    float rstd = rsqrtf(var + EPS_F);
    __half* dst = g_xn + (size_t)warp * Cc;
#pragma unroll
    for (int i = 0; i < 12; i++) {
        int c = lane + i * 32;
        dst[c] = __float2half((vals[i] - mean) * rstd * w[c] + b[c]);
    }
}

// ---------------- fused depthwise conv3x3 + BN + MLP LayerNorm ------------
// block = one pixel; 96 threads x 4 channels. Writes g_x2 (fp32, fc2 residual)
// and g_xn (fp16, fc1 input).
__global__ __launch_bounds__(96) void k_conv_bn_ln(
    const float* __restrict__ cw,
    const float* __restrict__ bnw, const float* __restrict__ bnb,
    const float* __restrict__ bnm, const float* __restrict__ bnv,
    const float* __restrict__ lnw, const float* __restrict__ lnb) {
    __shared__ float sms[3], sms2[3];
    const int p = blockIdx.x;
    const int b = p >> 12, yx = p & 4095;
    const int y = yx >> 6, x = yx & 63;
    const int tid = threadIdx.x, lane = tid & 31, wid = tid >> 5;
    const int c0 = tid * 4;

    float4 acc = make_float4(0.f, 0.f, 0.f, 0.f);
#pragma unroll
    for (int ky = 0; ky < 3; ky++) {
        int yy = y + ky - 1;
        if (yy < 0 || yy >= Hh) continue;
#pragma unroll
        for (int kx = 0; kx < 3; kx++) {
            int xx = x + kx - 1;
            if (xx < 0 || xx >= Ww) continue;
            float4 in = *(const float4*)&g_x1[((size_t)b * L_ + (size_t)yy * Ww + xx) * Cc + c0];
            int wo = ky * 3 + kx;
            acc.x += in.x * cw[(c0 + 0) * 9 + wo];
            acc.y += in.y * cw[(c0 + 1) * 9 + wo];
            acc.z += in.z * cw[(c0 + 2) * 9 + wo];
            acc.w += in.w * cw[(c0 + 3) * 9 + wo];
        }
    }
    float4 o;
    o.x = (acc.x - bnm[c0 + 0]) * (rsqrtf(bnv[c0 + 0] + 1e-5f) * bnw[c0 + 0]) + bnb[c0 + 0];
    o.y = (acc.y - bnm[c0 + 1]) * (rsqrtf(bnv[c0 + 1] + 1e-5f) * bnw[c0 + 1]) + bnb[c0 + 1];
    o.z = (acc.z - bnm[c0 + 2]) * (rsqrtf(bnv[c0 + 2] + 1e-5f) * bnw[c0 + 2]) + bnb[c0 + 2];
    o.w = (acc.w - bnm[c0 + 3]) * (rsqrtf(bnv[c0 + 3] + 1e-5f) * bnw[c0 + 3]) + bnb[c0 + 3];
    *(float4*)&g_x2[(size_t)p * Cc + c0] = o;

    // block-wide LN over 384 channels (3 warps)
    float s  = o.x + o.y + o.z + o.w;
    float s2 = o.x * o.x + o.y * o.y + o.z * o.z + o.w * o.w;
#pragma unroll
    for (int off = 16; off > 0; off >>= 1) {
        s  += __shfl_xor_sync(0xffffffffu, s,  off);
        s2 += __shfl_xor_sync(0xffffffffu, s2, off);
    }
    if (lane == 0) { sms[wid] = s; sms2[wid] = s2; }
    __syncthreads();
    float ts  = sms[0]  + sms[1]  + sms[2];
    float ts2 = sms2[0] + sms2[1] + sms2[2];
    float mean = ts * (1.f / Cc);
    float var  = ts2 * (1.f / Cc) - mean * mean;
    float rstd = rsqrtf(var + EPS_F);

    __half2* dst = (__half2*)(g_xn + (size_t)p * Cc + c0);
    dst[0] = __floats2half2_rn((o.x - mean) * rstd * lnw[c0 + 0] + lnb[c0 + 0],
                               (o.y - mean) * rstd * lnw[c0 + 1] + lnb[c0 + 1]);
    dst[1] = __floats2half2_rn((o.z - mean) * rstd * lnw[c0 + 2] + lnb[c0 + 2],
                               (o.w - mean) * rstd * lnw[c0 + 3] + lnb[c0 + 3]);
}

// ---------------- fp16 GEMM: 256 thr, 8 warps (2x4), 64x32 warp tiles ------
// EPI: 0 = qkv fp16 out with q-scale, 1 = GELU fp16 out,
//      2 = proj un-window+residual, 3 = residual add
template <int EPI, int M, int Nn, int K>
__device__ __forceinline__ void gemm_f16_body(const __half* __restrict__ A,
                                              const __half* __restrict__ Bw,
                                              const float* __restrict__ bias,
                                              float* __restrict__ Cout,
                                              const float* __restrict__ res) {
    extern __shared__ __align__(16) char smraw[];
    const int tid = threadIdx.x, lane = tid & 31, wid = tid >> 5;
    const int g = lane >> 2, tig = lane & 3;
    const int warp_m = wid >> 2, warp_n = wid & 3;    // 2 x 4 warps
    const int bm = blockIdx.y * 128, bn = blockIdx.x * 128;
    const int arow = tid >> 1, seg = tid & 1;         // 128 rows x 2 x 32B chunks

    const int r0 = bm + arow;
    const bool v0 = ((M % 128) == 0) || (r0 < M);
    const int sz0 = v0 ? 16 : 0;
    const __half* a0b = A  + (size_t)(v0 ? r0 : 0) * K + seg * 16;
    const __half* b0b = Bw + (size_t)(bn + arow) * K + seg * 16;
    const uint32_t smb = smem_u32(smraw);
    const uint32_t sa0 = smb + arow * 80 + seg * 32;
    const uint32_t sb0 = sa0 + 10240;

    const int a_row = (lane & 15), a_k = 8 * (lane >> 4);
    const int b_row = (lane >> 4) * 8 + (lane & 7), b_k = 8 * ((lane >> 3) & 1);
    const uint32_t aA = smb + ((warp_m * 64 + a_row) * 40 + a_k) * 2;
    const uint32_t aB = smb + 10240 + ((warp_n * 32 + b_row) * 40 + b_k) * 2;

    const int KT = K / 32;
    auto load_stage = [&](int s, int kt) {
        int kc = kt * 32;
        uint32_t so = (uint32_t)(s * GST_BYTES);
        cp_async16(sa0 + so,      a0b + kc,     sz0);
        cp_async16(sa0 + so + 16, a0b + kc + 8, sz0);
        cp_async16(sb0 + so,      b0b + kc,     16);
        cp_async16(sb0 + so + 16, b0b + kc + 8, 16);
        asm volatile("cp.async.commit_group;\n");
    };

    float acc[4][4][4];
#pragma unroll
    for (int mt = 0; mt < 4; mt++)
#pragma unroll
        for (int nt = 0; nt < 4; nt++)
#pragma unroll
            for (int r = 0; r < 4; r++) acc[mt][nt][r] = 0.f;

    load_stage(0, 0);
    load_stage(1, 1);

    for (int kt = 0; kt < KT; kt++) {
        if (kt + 1 < KT) {
            asm volatile("cp.async.wait_group 1;\n");
        } else {
            asm volatile("cp.async.wait_group 0;\n");
        }
        __syncthreads();
        if (kt + 2 < KT) load_stage((kt + 2) % 3, kt + 2);

        const uint32_t st = (uint32_t)((kt % 3) * GST_BYTES);
#pragma unroll
        for (int ks = 0; ks < 2; ks++) {
            const int kb = ks * 16;
            uint32_t afr[4][4], bfr[2][4];
#pragma unroll
            for (int mt = 0; mt < 4; mt++)
                ldsm_x4(afr[mt], aA + st + (mt * 16 * 40 + kb) * 2);
            ldsm_x4(bfr[0], aB + st + kb * 2);
            ldsm_x4(bfr[1], aB + st + (16 * 40 + kb) * 2);
#pragma unroll
            for (int mt = 0; mt < 4; mt++) {
                mma_f16(acc[mt][0], afr[mt], &bfr[0][0]);
                mma_f16(acc[mt][1], afr[mt], &bfr[0][2]);
                mma_f16(acc[mt][2], afr[mt], &bfr[1][0]);
                mma_f16(acc[mt][3], afr[mt], &bfr[1][2]);
            }
        }
    }

    // ---------- vectorized epilogue ----------
#pragma unroll
    for (int mt = 0; mt < 4; mt++) {
        const int m0 = bm + warp_m * 64 + mt * 16 + g;
        const int m1 = m0 + 8;
        const bool m0v = ((M % 128) == 0) || (m0 < M);
        const bool m1v = ((M % 128) == 0) || (m1 < M);
#pragma unroll
        for (int nt = 0; nt < 4; nt++) {
            const int nn = bn + warp_n * 32 + nt * 8 + tig * 2;
            const float2 bv = *(const float2*)&bias[nn];
            float p00 = acc[mt][nt][0] + bv.x, p01 = acc[mt][nt][1] + bv.y;
            float p10 = acc[mt][nt][2] + bv.x, p11 = acc[mt][nt][3] + bv.y;
            if (EPI == 0) {
                const float sc = ((nn % 96) < 32) ? SCALE_F : 1.f;
                if (m0v) *(__half2*)((__half*)Cout + (size_t)m0 * Nn + nn) =
                             __floats2half2_rn(p00 * sc, p01 * sc);
                if (m1v) *(__half2*)((__half*)Cout + (size_t)m1 * Nn + nn) =
                             __floats2half2_rn(p10 * sc, p11 * sc);
            } else if (EPI == 1) {
                float g00 = 0.5f * p00 * (1.f + erff(p00 * 0.70710678118654752f));
                float g01 = 0.5f * p01 * (1.f + erff(p01 * 0.70710678118654752f));
                float g10 = 0.5f * p10 * (1.f + erff(p10 * 0.70710678118654752f));
                float g11 = 0.5f * p11 * (1.f + erff(p11 * 0.70710678118654752f));
                if (m0v) *(__half2*)((__half*)Cout + (size_t)m0 * Nn + nn) =
                             __floats2half2_rn(g00, g01);
                if (m1v) *(__half2*)((__half*)Cout + (size_t)m1 * Nn + nn) =
                             __floats2half2_rn(g10, g11);
            } else if (EPI == 2) {
#pragma unroll
                for (int rr = 0; rr < 2; rr++) {
                    int m = rr ? m1 : m0;
                    if (((M % 128) != 0) && (m >= M)) continue;
                    int wi = m / Nt, t = m - wi * Nt;
                    int bb2 = wi / 25; int rem = wi - bb2 * 25;
                    int wy = rem / 5, wx = rem - wy * 5;
                    int ty = t / WSs, tx = t - ty * WSs;
                    int gy = wy * WSs + ty, gx = wx * WSs + tx;
                    if (gy < Hh && gx < Ww) {
                        size_t oo = ((size_t)bb2 * L_ + (size_t)gy * Ww + gx) * Cc + nn;
                        float2 rv = *(const float2*)&res[oo];
                        float2 ov;
                        ov.x = rv.x + (rr ? p10 : p00);
                        ov.y = rv.y + (rr ? p11 : p01);
                        *(float2*)&Cout[oo] = ov;
                    }
                }
            } else {
                if (m0v) {
                    size_t oo = (size_t)m0 * Nn + nn;
                    float2 rv = *(const float2*)&res[oo];
                    *(float2*)&Cout[oo] = make_float2(p00 + rv.x, p01 + rv.y);
                }
                if (m1v) {
                    size_t oo = (size_t)m1 * Nn + nn;
                    float2 rv = *(const float2*)&res[oo];
                    *(float2*)&Cout[oo] = make_float2(p10 + rv.x, p11 + rv.y);
                }
            }
        }
    }
}

__global__ __launch_bounds__(256, 2) void k_gemm_qkv(const float* __restrict__ b) {
    gemm_f16_body<0, M_ATT, QKVW, Cc>(g_xn, g_wq, b, (float*)g_qkv, nullptr);
}
__global__ __launch_bounds__(256, 2) void k_gemm_proj(const float* __restrict__ b,
                                                      const float* __restrict__ x) {
    gemm_f16_body<2, M_ATT, Cc, DH>(g_attno, g_wp, b, g_x1, x);
}
__global__ __launch_bounds__(256, 2) void k_gemm_fc1(const float* __restrict__ b) {
    gemm_f16_body<1, M_MLP, HID, Cc>(g_xn, g_w1, b, (float*)g_h1, nullptr);
}
__global__ __launch_bounds__(256, 2) void k_gemm_fc2(const float* __restrict__ b,
                                                     float* __restrict__ out) {
    gemm_f16_body<3, M_MLP, Cc, HID>(g_h1, g_w2, b, out, g_x2);
}

// ---------------- attention chunk step (online softmax) ----------------
template <int NTILES>
__device__ __forceinline__ void attn_chunk(
    int colbase, uint32_t smb, const uint32_t (&aq)[2][4],
    const float* __restrict__ bias_h, int row0, int row1, bool r0v, bool r1v,
    int lane, uint32_t vaddr0,
    float& m0, float& m1, float& l0, float& l1, float (&oacc)[4][4])
{
    const int tig = lane & 3;
    const int b_row = (lane >> 4) * 8 + (lane & 7), b_k = 8 * ((lane >> 3) & 1);

    float acc[NTILES][4];
#pragma unroll
    for (int np = 0; np < NTILES / 2; np++) {
        uint32_t ka = smb + (uint32_t)(NTP * AQ_STR * 2) +
                      ((colbase + np * 16 + b_row) * AQ_STR + b_k) * 2;
        uint32_t bf0[4], bf1[4];
        ldsm_x4(bf0, ka);
        ldsm_x4(bf1, ka + 32);
        float* a0 = acc[2 * np];
        float* a1 = acc[2 * np + 1];
        a0[0] = a0[1] = a0[2] = a0[3] = 0.f;
        a1[0] = a1[1] = a1[2] = a1[3] = 0.f;
        mma_f16(a0, aq[0], &bf0[0]);
        mma_f16(a0, aq[1], &bf1[0]);
        mma_f16(a1, aq[0], &bf0[2]);
        mma_f16(a1, aq[1], &bf1[2]);
    }

    float cm0 = -1e30f, cm1 = -1e30f;
#pragma unroll
    for (int nt = 0; nt < NTILES; nt++) {
        int col = colbase + nt * 8 + tig * 2;
        bool cv = col < Nt;
        float2 b0 = (cv && r0v) ? *(const float2*)(bias_h + (size_t)row0 * Nt + col)
                                : make_float2(0.f, 0.f);
        float2 b1 = (cv && r1v) ? *(const float2*)(bias_h + (size_t)row1 * Nt + col)
                                : make_float2(0.f, 0.f);
        acc[nt][0] = cv ? acc[nt][0] + b0.x : -1e30f;
        acc[nt][1] = cv ? acc[nt][1] + b0.y : -1e30f;
        acc[nt][2] = cv ? acc[nt][2] + b1.x : -1e30f;
        acc[nt][3] = cv ? acc[nt][3] + b1.y : -1e30f;
        cm0 = fmaxf(cm0, fmaxf(acc[nt][0], acc[nt][1]));
        cm1 = fmaxf(cm1, fmaxf(acc[nt][2], acc[nt][3]));
    }
    cm0 = fmaxf(cm0, __shfl_xor_sync(0xffffffffu, cm0, 1));
    cm0 = fmaxf(cm0, __shfl_xor_sync(0xffffffffu, cm0, 2));
    cm1 = fmaxf(cm1, __shfl_xor_sync(0xffffffffu, cm1, 1));
    cm1 = fmaxf(cm1, __shfl_xor_sync(0xffffffffu, cm1, 2));

    float mn0 = fmaxf(m0, cm0), mn1 = fmaxf(m1, cm1);
    float c0 = __expf(m0 - mn0), c1 = __expf(m1 - mn1);

    float s0 = 0.f, s1 = 0.f;
#pragma unroll
    for (int nt = 0; nt < NTILES; nt++) {
        acc[nt][0] = __expf(acc[nt][0] - mn0); s0 += acc[nt][0];
        acc[nt][1] = __expf(acc[nt][1] - mn0); s0 += acc[nt][1];
        acc[nt][2] = __expf(acc[nt][2] - mn1); s1 += acc[nt][2];
        acc[nt][3] = __expf(acc[nt][3] - mn1); s1 += acc[nt][3];
    }
    s0 += __shfl_xor_sync(0xffffffffu, s0, 1);
    s0 += __shfl_xor_sync(0xffffffffu, s0, 2);
    s1 += __shfl_xor_sync(0xffffffffu, s1, 1);
    s1 += __shfl_xor_sync(0xffffffffu, s1, 2);
    l0 = l0 * c0 + s0;
    l1 = l1 * c1 + s1;
    m0 = mn0; m1 = mn1;

#pragma unroll
    for (int nt = 0; nt < 4; nt++) {
        oacc[nt][0] *= c0; oacc[nt][1] *= c0;
        oacc[nt][2] *= c1; oacc[nt][3] *= c1;
    }

#pragma unroll
    for (int kk = 0; kk < NTILES / 2; kk++) {
        uint32_t pa[4];
        pa[0] = h2u(__floats2half2_rn(acc[2*kk  ][0], acc[2*kk  ][1]));
        pa[1] = h2u(__floats2half2_rn(acc[2*kk  ][2], acc[2*kk  ][3]));
        pa[2] = h2u(__floats2half2_rn(acc[2*kk+1][0], acc[2*kk+1][1]));
        pa[3] = h2u(__floats2half2_rn(acc[2*kk+1][2], acc[2*kk+1][3]));
        uint32_t vb0[4], vb1[4];
        uint32_t va = vaddr0 + (uint32_t)((colbase + kk * 16) * AQ_STR * 2);
        ldsm_x4_t(vb0, va);
        ldsm_x4_t(vb1, va + 32);
        mma_f16(oacc[0], pa, &vb0[0]);
        mma_f16(oacc[1], pa, &vb0[2]);
        mma_f16(oacc[2], pa, &vb1[0]);
        mma_f16(oacc[3], pa, &vb1[2]);
    }
}

// ---------------- fp16 tensor-core attention, 2-chunk online softmax ------
__global__ __launch_bounds__(256, 2) void k_attn() {
    extern __shared__ __align__(16) __half smh[];
    __half* qs = smh;
    __half* ks = smh + NTP * AQ_STR;
    __half* vs = smh + 2 * NTP * AQ_STR;

    const int blk = blockIdx.x;
    const int w = blk / HEADS, h = blk - w * HEADS;
    const __half* base = g_qkv + (size_t)w * Nt * QKVW + h * 96;
    const int tid = threadIdx.x, lane = tid & 31, wid = tid >> 5;
    const int g = lane >> 2, tig = lane & 3;
    const uint32_t smb = smem_u32(smh);

    for (int idx = tid; idx < NTP * 4; idx += 256) {
        int r = idx >> 2, d8 = (idx & 3) * 8;
        uint4 q4, k4, v4;
        if (r < Nt) {
            const __half* rp = base + (size_t)r * QKVW;
            q4 = *(const uint4*)(rp + d8);
            k4 = *(const uint4*)(rp + 32 + d8);
            v4 = *(const uint4*)(rp + 64 + d8);
        } else {
            q4 = k4 = v4 = make_uint4(0, 0, 0, 0);
        }
        *(uint4*)(qs + r * AQ_STR + d8) = q4;
        *(uint4*)(ks + r * AQ_STR + d8) = k4;
        *(uint4*)(vs + r * AQ_STR + d8) = v4;
    }
    __syncthreads();

    const float* bias_h = g_bias + (size_t)h * Nt * Nt;

    const int a_row = (lane & 15), a_k = 8 * (lane >> 4);
    const uint32_t vs_off = (uint32_t)(2 * NTP * AQ_STR * 2);
    const uint32_t vaddr0 = smb + vs_off + (((lane & 15)) * AQ_STR + 8 * (lane >> 4)) * 2;

    for (int tt = wid; tt < 13; tt += 8) {
        const int row0 = tt * 16 + g, row1 = row0 + 8;
        const bool r0v = row0 < Nt, r1v = row1 < Nt;

        uint32_t aq[2][4];
        {
            uint32_t qa = smb + ((tt * 16 + a_row) * AQ_STR + a_k) * 2;
            ldsm_x4(aq[0], qa);
            ldsm_x4(aq[1], qa + 32);
        }

        float m0 = -1e30f, m1 = -1e30f, l0 = 0.f, l1 = 0.f;
        float oacc[4][4];
#pragma unroll
        for (int nt = 0; nt < 4; nt++)
            oacc[nt][0] = oacc[nt][1] = oacc[nt][2] = oacc[nt][3] = 0.f;

        attn_chunk<14>(0,   smb, aq, bias_h, row0, row1, r0v, r1v, lane, vaddr0,
                       m0, m1, l0, l1, oacc);
        attn_chunk<12>(112, smb, aq, bias_h, row0, row1, r0v, r1v, lane, vaddr0,
                       m0, m1, l0, l1, oacc);

        const float inv0 = 1.f / l0, inv1 = 1.f / l1;
        if (r0v) {
            __half* op = g_attno + ((size_t)(w * Nt + row0)) * DH + h * KD;
#pragma unroll
            for (int nt = 0; nt < 4; nt++)
                *(__half2*)(op + nt * 8 + tig * 2) =
                    __floats2half2_rn(oacc[nt][0] * inv0, oacc[nt][1] * inv0);
        }
        if (r1v) {
            __half* op = g_attno + ((size_t)(w * Nt + row1)) * DH + h * KD;
#pragma unroll
            for (int nt = 0; nt < 4; nt++)
                *(__half2*)(op + nt * 8 + tig * 2) =
                    __floats2half2_rn(oacc[nt][2] * inv1, oacc[nt][3] * inv1);
        }
    }
}

// ---------------- launcher ----------------
extern "C" void kernel_launch(void* const* d_in, const int* in_sizes, int n_in,
                              void* d_out, int out_size) {
    const float* x        = (const float*)d_in[0];
    const float* ln_aw    = (const float*)d_in[1];
    const float* ln_ab    = (const float*)d_in[2];
    const float* qkv_w    = (const float*)d_in[3];
    const float* qkv_b    = (const float*)d_in[4];
    const float* proj_w   = (const float*)d_in[5];
    const float* proj_b   = (const float*)d_in[6];
    const float* attn_bia = (const float*)d_in[7];
    const float* conv_w   = (const float*)d_in[8];
    const float* bn_w     = (const float*)d_in[9];
    const float* bn_b     = (const float*)d_in[10];
    const float* bn_m     = (const float*)d_in[11];
    const float* bn_v     = (const float*)d_in[12];
    const float* ln_mw    = (const float*)d_in[13];
    const float* ln_mb    = (const float*)d_in[14];
    const float* fc1_w    = (const float*)d_in[15];
    const float* fc1_b    = (const float*)d_in[16];
    const float* fc2_w    = (const float*)d_in[17];
    const float* fc2_b    = (const float*)d_in[18];
    const int*   bias_idx = (const int*)d_in[19];
    float* out = (float*)d_out;

    int n_off = in_sizes[7] / HEADS;

    cudaFuncSetAttribute(k_gemm_qkv,  cudaFuncAttributeMaxDynamicSharedMemorySize, SMEM_GEMM);
    cudaFuncSetAttribute(k_gemm_proj, cudaFuncAttributeMaxDynamicSharedMemorySize, SMEM_GEMM);
    cudaFuncSetAttribute(k_gemm_fc1,  cudaFuncAttributeMaxDynamicSharedMemorySize, SMEM_GEMM);
    cudaFuncSetAttribute(k_gemm_fc2,  cudaFuncAttributeMaxDynamicSharedMemorySize, SMEM_GEMM);
    cudaFuncSetAttribute(k_attn,      cudaFuncAttributeMaxDynamicSharedMemorySize, SMEM_ATTN);

    {
        int n0 = QKVW * Cc / 4, n1 = Cc * DH / 4, n2 = HID * Cc / 4, n3 = Cc * HID / 4;
        int tot = n0 + n1 + n2 + n3;
        k_half_all<<<(tot + 255) / 256, 256>>>((const float4*)qkv_w, n0,
                                               (const float4*)proj_w, n1,
                                               (const float4*)fc1_w, n2,
                                               (const float4*)fc2_w, n3);
    }
    {
        int tot = HEADS * Nt * Nt;
        k_bias_expand<<<(tot + 255) / 256, 256>>>(attn_bia, bias_idx, n_off);
    }
    k_win_ln<<<M_ATT / 8, 256>>>(x, ln_aw, ln_ab);
    k_gemm_qkv<<<dim3(QKVW / 128, (M_ATT + 127) / 128), 256, SMEM_GEMM>>>(qkv_b);
    k_attn<<<NW * HEADS, 256, SMEM_ATTN>>>();
    k_gemm_proj<<<dim3(Cc / 128, (M_ATT + 127) / 128), 256, SMEM_GEMM>>>(proj_b, x);
    k_conv_bn_ln<<<B_ * L_, 96>>>(conv_w, bn_w, bn_b, bn_m, bn_v, ln_mw, ln_mb);
    k_gemm_fc1<<<dim3(HID / 128, M_MLP / 128), 256, SMEM_GEMM>>>(fc1_b);
    k_gemm_fc2<<<dim3(Cc / 128, M_MLP / 128), 256, SMEM_GEMM>>>(fc2_b, out);
}

// round 14
// speedup vs baseline: 1.0710x; 1.0710x over previous
#include <cuda_runtime.h>
#include <cuda_fp16.h>
#include <math.h>
#include <stdint.h>

// ---------------- problem constants ----------------
#define B_      8
#define Hh      64
#define Ww      64
#define Cc      384
#define HEADS   12
#define WSs     14
#define KD      32
#define Nt      196
#define NW      200
#define M_ATT   39200
#define L_      4096
#define M_MLP   32768
#define HID     1536
#define DH      384
#define QKVW    1152
#define SCALE_F 0.17677669529663687f
#define EPS_F   1e-5f

// attention tiling
#define NTP        208
#define AQ_STR     40
#define SMEM_ATTN  (3 * NTP * AQ_STR * 2)

// fp16 gemm smem: 3 stages x (A[128][40] + B[128][40]) halfs
#define GST_BYTES   20480
#define SMEM_GEMM   (3 * GST_BYTES)

// ---------------- scratch ----------------
__device__ __align__(16) __half g_xn[M_ATT * Cc];
__device__ __align__(16) __half g_qkv[(size_t)M_ATT * QKVW];
__device__ __align__(16) __half g_attno[M_ATT * Cc];
__device__ float  g_x1[M_MLP * Cc];
__device__ float  g_x2[M_MLP * Cc];
__device__ __align__(16) __half g_h1[(size_t)M_MLP * HID];
__device__ float  g_bias[HEADS * Nt * Nt];
__device__ __align__(16) __half g_wq[QKVW * Cc];
__device__ __align__(16) __half g_wp[Cc * DH];
__device__ __align__(16) __half g_w1[HID * Cc];
__device__ __align__(16) __half g_w2[Cc * HID];

// ---------------- helpers ----------------
__device__ __forceinline__ void mma_f16(float* c, const uint32_t* a, const uint32_t* b) {
    asm volatile(
        "mma.sync.aligned.m16n8k16.row.col.f32.f16.f16.f32 "
        "{%0,%1,%2,%3}, {%4,%5,%6,%7}, {%8,%9}, {%0,%1,%2,%3};\n"
        : "+f"(c[0]), "+f"(c[1]), "+f"(c[2]), "+f"(c[3])
        : "r"(a[0]), "r"(a[1]), "r"(a[2]), "r"(a[3]), "r"(b[0]), "r"(b[1]));
}

__device__ __forceinline__ void ldsm_x4(uint32_t* r, uint32_t saddr) {
    asm volatile("ldmatrix.sync.aligned.m8n8.x4.shared.b16 {%0,%1,%2,%3}, [%4];"
                 : "=r"(r[0]), "=r"(r[1]), "=r"(r[2]), "=r"(r[3]) : "r"(saddr));
}

__device__ __forceinline__ void ldsm_x4_t(uint32_t* r, uint32_t saddr) {
    asm volatile("ldmatrix.sync.aligned.m8n8.x4.trans.shared.b16 {%0,%1,%2,%3}, [%4];"
                 : "=r"(r[0]), "=r"(r[1]), "=r"(r[2]), "=r"(r[3]) : "r"(saddr));
}

__device__ __forceinline__ void cp_async16(uint32_t saddr, const void* gptr, int srcbytes) {
    asm volatile("cp.async.cg.shared.global [%0], [%1], 16, %2;\n"
                 :: "r"(saddr), "l"(gptr), "r"(srcbytes));
}

__device__ __forceinline__ uint32_t smem_u32(const void* p) {
    uint32_t a;
    asm("{ .reg .u64 t; cvta.to.shared.u64 t, %1; cvt.u32.u64 %0, t; }" : "=r"(a) : "l"(p));
    return a;
}

__device__ __forceinline__ uint32_t h2u(__half2 h) {
    return *(uint32_t*)&h;
}

// ---------------- weight conversion fp32 -> fp16 ----------------
__global__ void k_half_all(const float4* __restrict__ s0, int n0,
                           const float4* __restrict__ s1, int n1,
                           const float4* __restrict__ s2, int n2,
                           const float4* __restrict__ s3, int n3) {
    int i = blockIdx.x * blockDim.x + threadIdx.x;
    const float4* src; __half* dst; int j = i;
    if (j < n0) { src = s0; dst = g_wq; }
    else if ((j -= n0) < n1) { src = s1; dst = g_wp; }
    else if ((j -= n1) < n2) { src = s2; dst = g_w1; }
    else if ((j -= n2) < n3) { src = s3; dst = g_w2; }
    else return;
    float4 v = src[j];
    __half2* d2 = (__half2*)(dst + 4 * (size_t)j);
    d2[0] = __floats2half2_rn(v.x, v.y);
    d2[1] = __floats2half2_rn(v.z, v.w);
}

// ---------------- kernel: expand bias table ----------------
__global__ void k_bias_expand(const float* __restrict__ ab,
                              const int* __restrict__ bidx, int n_off) {
    int i = blockIdx.x * blockDim.x + threadIdx.x;
    if (i >= HEADS * Nt * Nt) return;
    int h  = i / (Nt * Nt);
    int ij = i - h * (Nt * Nt);
    g_bias[i] = ab[h * n_off + bidx[ij]];
}

// ---------------- kernel: window partition + LayerNorm (fp16 out) ---------
__global__ void k_win_ln(const float* __restrict__ x,
                         const float* __restrict__ w,
                         const float* __restrict__ b) {
    int warp = (blockIdx.x * blockDim.x + threadIdx.x) >> 5;
    int lane = threadIdx.x & 31;
    if (warp >= M_ATT) return;
    int wi = warp / Nt, t = warp - wi * Nt;
    int bb = wi / 25; int rem = wi - bb * 25;
    int wy = rem / 5, wx = rem - wy * 5;
    int ty = t / WSs, tx = t - ty * WSs;
    int gy = wy * WSs + ty, gx = wx * WSs + tx;
    bool valid = (gy < Hh) && (gx < Ww);
    const float* src = x + ((size_t)bb * L_ + (size_t)gy * Ww + gx) * Cc;

    float vals[12];
    float s = 0.f, s2 = 0.f;
#pragma unroll
    for (int i = 0; i < 12; i++) {
        float v = valid ? src[lane + i * 32] : 0.f;
        vals[i] = v; s += v; s2 += v * v;
    }
#pragma unroll
    for (int o = 16; o > 0; o >>= 1) {
        s  += __shfl_xor_sync(0xffffffffu, s,  o);
        s2 += __shfl_xor_sync(0xffffffffu, s2, o);
    }
    float mean = s * (1.f / Cc);
    float var  = s2 * (1.f / Cc) - mean * mean;
    float rstd = rsqrtf(var + EPS_F);
    __half* dst = g_xn + (size_t)warp * Cc;
#pragma unroll
    for (int i = 0; i < 12; i++) {
        int c = lane + i * 32;
        dst[c] = __float2half((vals[i] - mean) * rstd * w[c] + b[c]);
    }
}

// ---------------- fused depthwise conv3x3 + BN + MLP LayerNorm ------------
__global__ __launch_bounds__(96) void k_conv_bn_ln(
    const float* __restrict__ cw,
    const float* __restrict__ bnw, const float* __restrict__ bnb,
    const float* __restrict__ bnm, const float* __restrict__ bnv,
    const float* __restrict__ lnw, const float* __restrict__ lnb) {
    __shared__ float sms[3], sms2[3];
    const int p = blockIdx.x;
    const int b = p >> 12, yx = p & 4095;
    const int y = yx >> 6, x = yx & 63;
    const int tid = threadIdx.x, lane = tid & 31, wid = tid >> 5;
    const int c0 = tid * 4;

    float4 acc = make_float4(0.f, 0.f, 0.f, 0.f);
#pragma unroll
    for (int ky = 0; ky < 3; ky++) {
        int yy = y + ky - 1;
        if (yy < 0 || yy >= Hh) continue;
#pragma unroll
        for (int kx = 0; kx < 3; kx++) {
            int xx = x + kx - 1;
            if (xx < 0 || xx >= Ww) continue;
            float4 in = *(const float4*)&g_x1[((size_t)b * L_ + (size_t)yy * Ww + xx) * Cc + c0];
            int wo = ky * 3 + kx;
            acc.x += in.x * cw[(c0 + 0) * 9 + wo];
            acc.y += in.y * cw[(c0 + 1) * 9 + wo];
            acc.z += in.z * cw[(c0 + 2) * 9 + wo];
            acc.w += in.w * cw[(c0 + 3) * 9 + wo];
        }
    }
    float4 o;
    o.x = (acc.x - bnm[c0 + 0]) * (rsqrtf(bnv[c0 + 0] + 1e-5f) * bnw[c0 + 0]) + bnb[c0 + 0];
    o.y = (acc.y - bnm[c0 + 1]) * (rsqrtf(bnv[c0 + 1] + 1e-5f) * bnw[c0 + 1]) + bnb[c0 + 1];
    o.z = (acc.z - bnm[c0 + 2]) * (rsqrtf(bnv[c0 + 2] + 1e-5f) * bnw[c0 + 2]) + bnb[c0 + 2];
    o.w = (acc.w - bnm[c0 + 3]) * (rsqrtf(bnv[c0 + 3] + 1e-5f) * bnw[c0 + 3]) + bnb[c0 + 3];
    *(float4*)&g_x2[(size_t)p * Cc + c0] = o;

    float s  = o.x + o.y + o.z + o.w;
    float s2 = o.x * o.x + o.y * o.y + o.z * o.z + o.w * o.w;
#pragma unroll
    for (int off = 16; off > 0; off >>= 1) {
        s  += __shfl_xor_sync(0xffffffffu, s,  off);
        s2 += __shfl_xor_sync(0xffffffffu, s2, off);
    }
    if (lane == 0) { sms[wid] = s; sms2[wid] = s2; }
    __syncthreads();
    float ts  = sms[0]  + sms[1]  + sms[2];
    float ts2 = sms2[0] + sms2[1] + sms2[2];
    float mean = ts * (1.f / Cc);
    float var  = ts2 * (1.f / Cc) - mean * mean;
    float rstd = rsqrtf(var + EPS_F);

    __half2* dst = (__half2*)(g_xn + (size_t)p * Cc + c0);
    dst[0] = __floats2half2_rn((o.x - mean) * rstd * lnw[c0 + 0] + lnb[c0 + 0],
                               (o.y - mean) * rstd * lnw[c0 + 1] + lnb[c0 + 1]);
    dst[1] = __floats2half2_rn((o.z - mean) * rstd * lnw[c0 + 2] + lnb[c0 + 2],
                               (o.w - mean) * rstd * lnw[c0 + 3] + lnb[c0 + 3]);
}

// ---------------- fp16 GEMM: 512 thr, 16 warps (4x4), 32x32 warp tiles -----
// (round-12 configuration, restored)
// EPI: 0 = qkv fp16 out with q-scale, 1 = GELU fp16 out,
//      2 = proj un-window+residual, 3 = residual add
template <int EPI, int M, int Nn, int K>
__device__ __forceinline__ void gemm_f16_body(const __half* __restrict__ A,
                                              const __half* __restrict__ Bw,
                                              const float* __restrict__ bias,
                                              float* __restrict__ Cout,
                                              const float* __restrict__ res) {
    extern __shared__ __align__(16) char smraw[];
    const int tid = threadIdx.x, lane = tid & 31, wid = tid >> 5;
    const int g = lane >> 2, tig = lane & 3;
    const int warp_m = wid >> 2, warp_n = wid & 3;
    const int bm = blockIdx.y * 128, bn = blockIdx.x * 128;
    const int arow = tid >> 2, seg = tid & 3;

    const int r0 = bm + arow;
    const bool v0 = ((M % 128) == 0) || (r0 < M);
    const int sz0 = v0 ? 16 : 0;
    const __half* a0b = A  + (size_t)(v0 ? r0 : 0) * K + seg * 8;
    const __half* b0b = Bw + (size_t)(bn + arow) * K + seg * 8;
    const uint32_t smb = smem_u32(smraw);
    const uint32_t sa0 = smb + arow * 80 + seg * 16;
    const uint32_t sb0 = sa0 + 10240;

    const int a_row = (lane & 15), a_k = 8 * (lane >> 4);
    const int b_row = (lane >> 4) * 8 + (lane & 7), b_k = 8 * ((lane >> 3) & 1);
    const uint32_t aA = smb + ((warp_m * 32 + a_row) * 40 + a_k) * 2;
    const uint32_t aB = smb + 10240 + ((warp_n * 32 + b_row) * 40 + b_k) * 2;

    const int KT = K / 32;
    auto load_stage = [&](int s, int kt) {
        int kc = kt * 32;
        uint32_t so = (uint32_t)(s * GST_BYTES);
        cp_async16(sa0 + so, a0b + kc, sz0);
        cp_async16(sb0 + so, b0b + kc, 16);
        asm volatile("cp.async.commit_group;\n");
    };

    float acc[2][4][4];
#pragma unroll
    for (int mt = 0; mt < 2; mt++)
#pragma unroll
        for (int nt = 0; nt < 4; nt++)
#pragma unroll
            for (int r = 0; r < 4; r++) acc[mt][nt][r] = 0.f;

    load_stage(0, 0);
    load_stage(1, 1);

    for (int kt = 0; kt < KT; kt++) {
        if (kt + 1 < KT) {
            asm volatile("cp.async.wait_group 1;\n");
        } else {
            asm volatile("cp.async.wait_group 0;\n");
        }
        __syncthreads();
        if (kt + 2 < KT) load_stage((kt + 2) % 3, kt + 2);

        const uint32_t st = (uint32_t)((kt % 3) * GST_BYTES);
#pragma unroll
        for (int ks = 0; ks < 2; ks++) {
            const int kb = ks * 16;
            uint32_t afr[2][4], bfr2[2][4];
            ldsm_x4(afr[0], aA + st + kb * 2);
            ldsm_x4(afr[1], aA + st + (16 * 40 + kb) * 2);
            ldsm_x4(bfr2[0], aB + st + kb * 2);
            ldsm_x4(bfr2[1], aB + st + (16 * 40 + kb) * 2);
#pragma unroll
            for (int mt = 0; mt < 2; mt++) {
                mma_f16(acc[mt][0], afr[mt], &bfr2[0][0]);
                mma_f16(acc[mt][1], afr[mt], &bfr2[0][2]);
                mma_f16(acc[mt][2], afr[mt], &bfr2[1][0]);
                mma_f16(acc[mt][3], afr[mt], &bfr2[1][2]);
            }
        }
    }

    // ---------- vectorized epilogue ----------
#pragma unroll
    for (int mt = 0; mt < 2; mt++) {
        const int m0 = bm + warp_m * 32 + mt * 16 + g;
        const int m1 = m0 + 8;
        const bool m0v = ((M % 128) == 0) || (m0 < M);
        const bool m1v = ((M % 128) == 0) || (m1 < M);
#pragma unroll
        for (int nt = 0; nt < 4; nt++) {
            const int nn = bn + warp_n * 32 + nt * 8 + tig * 2;
            const float2 bv = *(const float2*)&bias[nn];
            float p00 = acc[mt][nt][0] + bv.x, p01 = acc[mt][nt][1] + bv.y;
            float p10 = acc[mt][nt][2] + bv.x, p11 = acc[mt][nt][3] + bv.y;
            if (EPI == 0) {
                const float sc = ((nn % 96) < 32) ? SCALE_F : 1.f;
                if (m0v) *(__half2*)((__half*)Cout + (size_t)m0 * Nn + nn) =
                             __floats2half2_rn(p00 * sc, p01 * sc);
                if (m1v) *(__half2*)((__half*)Cout + (size_t)m1 * Nn + nn) =
                             __floats2half2_rn(p10 * sc, p11 * sc);
            } else if (EPI == 1) {
                float g00 = 0.5f * p00 * (1.f + erff(p00 * 0.70710678118654752f));
                float g01 = 0.5f * p01 * (1.f + erff(p01 * 0.70710678118654752f));
                float g10 = 0.5f * p10 * (1.f + erff(p10 * 0.70710678118654752f));
                float g11 = 0.5f * p11 * (1.f + erff(p11 * 0.70710678118654752f));
                if (m0v) *(__half2*)((__half*)Cout + (size_t)m0 * Nn + nn) =
                             __floats2half2_rn(g00, g01);
                if (m1v) *(__half2*)((__half*)Cout + (size_t)m1 * Nn + nn) =
                             __floats2half2_rn(g10, g11);
            } else if (EPI == 2) {
#pragma unroll
                for (int rr = 0; rr < 2; rr++) {
                    int m = rr ? m1 : m0;
                    if (((M % 128) != 0) && (m >= M)) continue;
                    int wi = m / Nt, t = m - wi * Nt;
                    int bb2 = wi / 25; int rem = wi - bb2 * 25;
                    int wy = rem / 5, wx = rem - wy * 5;
                    int ty = t / WSs, tx = t - ty * WSs;
                    int gy = wy * WSs + ty, gx = wx * WSs + tx;
                    if (gy < Hh && gx < Ww) {
                        size_t oo = ((size_t)bb2 * L_ + (size_t)gy * Ww + gx) * Cc + nn;
                        float2 rv = *(const float2*)&res[oo];
                        float2 ov;
                        ov.x = rv.x + (rr ? p10 : p00);
                        ov.y = rv.y + (rr ? p11 : p01);
                        *(float2*)&Cout[oo] = ov;
                    }
                }
            } else {
                if (m0v) {
                    size_t oo = (size_t)m0 * Nn + nn;
                    float2 rv = *(const float2*)&res[oo];
                    *(float2*)&Cout[oo] = make_float2(p00 + rv.x, p01 + rv.y);
                }
                if (m1v) {
                    size_t oo = (size_t)m1 * Nn + nn;
                    float2 rv = *(const float2*)&res[oo];
                    *(float2*)&Cout[oo] = make_float2(p10 + rv.x, p11 + rv.y);
                }
            }
        }
    }
}

__global__ __launch_bounds__(512, 2) void k_gemm_qkv(const float* __restrict__ b) {
    gemm_f16_body<0, M_ATT, QKVW, Cc>(g_xn, g_wq, b, (float*)g_qkv, nullptr);
}
__global__ __launch_bounds__(512, 2) void k_gemm_proj(const float* __restrict__ b,
                                                      const float* __restrict__ x) {
    gemm_f16_body<2, M_ATT, Cc, DH>(g_attno, g_wp, b, g_x1, x);
}
__global__ __launch_bounds__(512, 2) void k_gemm_fc1(const float* __restrict__ b) {
    gemm_f16_body<1, M_MLP, HID, Cc>(g_xn, g_w1, b, (float*)g_h1, nullptr);
}
__global__ __launch_bounds__(512, 2) void k_gemm_fc2(const float* __restrict__ b,
                                                     float* __restrict__ out) {
    gemm_f16_body<3, M_MLP, Cc, HID>(g_h1, g_w2, b, out, g_x2);
}

// ---------------- attention chunk step (online softmax) ----------------
template <int NTILES>
__device__ __forceinline__ void attn_chunk(
    int colbase, uint32_t smb, const uint32_t (&aq)[2][4],
    const float* __restrict__ bias_h, int row0, int row1, bool r0v, bool r1v,
    int lane, uint32_t vaddr0,
    float& m0, float& m1, float& l0, float& l1, float (&oacc)[4][4])
{
    const int tig = lane & 3;
    const int b_row = (lane >> 4) * 8 + (lane & 7), b_k = 8 * ((lane >> 3) & 1);

    float acc[NTILES][4];
#pragma unroll
    for (int np = 0; np < NTILES / 2; np++) {
        uint32_t ka = smb + (uint32_t)(NTP * AQ_STR * 2) +
                      ((colbase + np * 16 + b_row) * AQ_STR + b_k) * 2;
        uint32_t bf0[4], bf1[4];
        ldsm_x4(bf0, ka);
        ldsm_x4(bf1, ka + 32);
        float* a0 = acc[2 * np];
        float* a1 = acc[2 * np + 1];
        a0[0] = a0[1] = a0[2] = a0[3] = 0.f;
        a1[0] = a1[1] = a1[2] = a1[3] = 0.f;
        mma_f16(a0, aq[0], &bf0[0]);
        mma_f16(a0, aq[1], &bf1[0]);
        mma_f16(a1, aq[0], &bf0[2]);
        mma_f16(a1, aq[1], &bf1[2]);
    }

    float cm0 = -1e30f, cm1 = -1e30f;
#pragma unroll
    for (int nt = 0; nt < NTILES; nt++) {
        int col = colbase + nt * 8 + tig * 2;
        bool cv = col < Nt;
        float2 b0 = (cv && r0v) ? *(const float2*)(bias_h + (size_t)row0 * Nt + col)
                                : make_float2(0.f, 0.f);
        float2 b1 = (cv && r1v) ? *(const float2*)(bias_h + (size_t)row1 * Nt + col)
                                : make_float2(0.f, 0.f);
        acc[nt][0] = cv ? acc[nt][0] + b0.x : -1e30f;
        acc[nt][1] = cv ? acc[nt][1] + b0.y : -1e30f;
        acc[nt][2] = cv ? acc[nt][2] + b1.x : -1e30f;
        acc[nt][3] = cv ? acc[nt][3] + b1.y : -1e30f;
        cm0 = fmaxf(cm0, fmaxf(acc[nt][0], acc[nt][1]));
        cm1 = fmaxf(cm1, fmaxf(acc[nt][2], acc[nt][3]));
    }
    cm0 = fmaxf(cm0, __shfl_xor_sync(0xffffffffu, cm0, 1));
    cm0 = fmaxf(cm0, __shfl_xor_sync(0xffffffffu, cm0, 2));
    cm1 = fmaxf(cm1, __shfl_xor_sync(0xffffffffu, cm1, 1));
    cm1 = fmaxf(cm1, __shfl_xor_sync(0xffffffffu, cm1, 2));

    float mn0 = fmaxf(m0, cm0), mn1 = fmaxf(m1, cm1);
    float c0 = __expf(m0 - mn0), c1 = __expf(m1 - mn1);

    float s0 = 0.f, s1 = 0.f;
#pragma unroll
    for (int nt = 0; nt < NTILES; nt++) {
        acc[nt][0] = __expf(acc[nt][0] - mn0); s0 += acc[nt][0];
        acc[nt][1] = __expf(acc[nt][1] - mn0); s0 += acc[nt][1];
        acc[nt][2] = __expf(acc[nt][2] - mn1); s1 += acc[nt][2];
        acc[nt][3] = __expf(acc[nt][3] - mn1); s1 += acc[nt][3];
    }
    s0 += __shfl_xor_sync(0xffffffffu, s0, 1);
    s0 += __shfl_xor_sync(0xffffffffu, s0, 2);
    s1 += __shfl_xor_sync(0xffffffffu, s1, 1);
    s1 += __shfl_xor_sync(0xffffffffu, s1, 2);
    l0 = l0 * c0 + s0;
    l1 = l1 * c1 + s1;
    m0 = mn0; m1 = mn1;

#pragma unroll
    for (int nt = 0; nt < 4; nt++) {
        oacc[nt][0] *= c0; oacc[nt][1] *= c0;
        oacc[nt][2] *= c1; oacc[nt][3] *= c1;
    }

#pragma unroll
    for (int kk = 0; kk < NTILES / 2; kk++) {
        uint32_t pa[4];
        pa[0] = h2u(__floats2half2_rn(acc[2*kk  ][0], acc[2*kk  ][1]));
        pa[1] = h2u(__floats2half2_rn(acc[2*kk  ][2], acc[2*kk  ][3]));
        pa[2] = h2u(__floats2half2_rn(acc[2*kk+1][0], acc[2*kk+1][1]));
        pa[3] = h2u(__floats2half2_rn(acc[2*kk+1][2], acc[2*kk+1][3]));
        uint32_t vb0[4], vb1[4];
        uint32_t va = vaddr0 + (uint32_t)((colbase + kk * 16) * AQ_STR * 2);
        ldsm_x4_t(vb0, va);
        ldsm_x4_t(vb1, va + 32);
        mma_f16(oacc[0], pa, &vb0[0]);
        mma_f16(oacc[1], pa, &vb0[2]);
        mma_f16(oacc[2], pa, &vb1[0]);
        mma_f16(oacc[3], pa, &vb1[2]);
    }
}

// ---------------- fp16 tensor-core attention, 2-chunk online softmax ------
__global__ __launch_bounds__(256, 2) void k_attn() {
    extern __shared__ __align__(16) __half smh[];
    __half* qs = smh;
    __half* ks = smh + NTP * AQ_STR;
    __half* vs = smh + 2 * NTP * AQ_STR;

    const int blk = blockIdx.x;
    const int w = blk / HEADS, h = blk - w * HEADS;
    const __half* base = g_qkv + (size_t)w * Nt * QKVW + h * 96;
    const int tid = threadIdx.x, lane = tid & 31, wid = tid >> 5;
    const int g = lane >> 2, tig = lane & 3;
    const uint32_t smb = smem_u32(smh);

    for (int idx = tid; idx < NTP * 4; idx += 256) {
        int r = idx >> 2, d8 = (idx & 3) * 8;
        uint4 q4, k4, v4;
        if (r < Nt) {
            const __half* rp = base + (size_t)r * QKVW;
            q4 = *(const uint4*)(rp + d8);
            k4 = *(const uint4*)(rp + 32 + d8);
            v4 = *(const uint4*)(rp + 64 + d8);
        } else {
            q4 = k4 = v4 = make_uint4(0, 0, 0, 0);
        }
        *(uint4*)(qs + r * AQ_STR + d8) = q4;
        *(uint4*)(ks + r * AQ_STR + d8) = k4;
        *(uint4*)(vs + r * AQ_STR + d8) = v4;
    }
    __syncthreads();

    const float* bias_h = g_bias + (size_t)h * Nt * Nt;

    const int a_row = (lane & 15), a_k = 8 * (lane >> 4);
    const uint32_t vs_off = (uint32_t)(2 * NTP * AQ_STR * 2);
    const uint32_t vaddr0 = smb + vs_off + (((lane & 15)) * AQ_STR + 8 * (lane >> 4)) * 2;

    for (int tt = wid; tt < 13; tt += 8) {
        const int row0 = tt * 16 + g, row1 = row0 + 8;
        const bool r0v = row0 < Nt, r1v = row1 < Nt;

        uint32_t aq[2][4];
        {
            uint32_t qa = smb + ((tt * 16 + a_row) * AQ_STR + a_k) * 2;
            ldsm_x4(aq[0], qa);
            ldsm_x4(aq[1], qa + 32);
        }

        float m0 = -1e30f, m1 = -1e30f, l0 = 0.f, l1 = 0.f;
        float oacc[4][4];
#pragma unroll
        for (int nt = 0; nt < 4; nt++)
            oacc[nt][0] = oacc[nt][1] = oacc[nt][2] = oacc[nt][3] = 0.f;

        attn_chunk<14>(0,   smb, aq, bias_h, row0, row1, r0v, r1v, lane, vaddr0,
                       m0, m1, l0, l1, oacc);
        attn_chunk<12>(112, smb, aq, bias_h, row0, row1, r0v, r1v, lane, vaddr0,
                       m0, m1, l0, l1, oacc);

        const float inv0 = 1.f / l0, inv1 = 1.f / l1;
        if (r0v) {
            __half* op = g_attno + ((size_t)(w * Nt + row0)) * DH + h * KD;
#pragma unroll
            for (int nt = 0; nt < 4; nt++)
                *(__half2*)(op + nt * 8 + tig * 2) =
                    __floats2half2_rn(oacc[nt][0] * inv0, oacc[nt][1] * inv0);
        }
        if (r1v) {
            __half* op = g_attno + ((size_t)(w * Nt + row1)) * DH + h * KD;
#pragma unroll
            for (int nt = 0; nt < 4; nt++)
                *(__half2*)(op + nt * 8 + tig * 2) =
                    __floats2half2_rn(oacc[nt][2] * inv1, oacc[nt][3] * inv1);
        }
    }
}

// ---------------- launcher ----------------
extern "C" void kernel_launch(void* const* d_in, const int* in_sizes, int n_in,
                              void* d_out, int out_size) {
    const float* x        = (const float*)d_in[0];
    const float* ln_aw    = (const float*)d_in[1];
    const float* ln_ab    = (const float*)d_in[2];
    const float* qkv_w    = (const float*)d_in[3];
    const float* qkv_b    = (const float*)d_in[4];
    const float* proj_w   = (const float*)d_in[5];
    const float* proj_b   = (const float*)d_in[6];
    const float* attn_bia = (const float*)d_in[7];
    const float* conv_w   = (const float*)d_in[8];
    const float* bn_w     = (const float*)d_in[9];
    const float* bn_b     = (const float*)d_in[10];
    const float* bn_m     = (const float*)d_in[11];
    const float* bn_v     = (const float*)d_in[12];
    const float* ln_mw    = (const float*)d_in[13];
    const float* ln_mb    = (const float*)d_in[14];
    const float* fc1_w    = (const float*)d_in[15];
    const float* fc1_b    = (const float*)d_in[16];
    const float* fc2_w    = (const float*)d_in[17];
    const float* fc2_b    = (const float*)d_in[18];
    const int*   bias_idx = (const int*)d_in[19];
    float* out = (float*)d_out;

    int n_off = in_sizes[7] / HEADS;

    cudaFuncSetAttribute(k_gemm_qkv,  cudaFuncAttributeMaxDynamicSharedMemorySize, SMEM_GEMM);
    cudaFuncSetAttribute(k_gemm_proj, cudaFuncAttributeMaxDynamicSharedMemorySize, SMEM_GEMM);
    cudaFuncSetAttribute(k_gemm_fc1,  cudaFuncAttributeMaxDynamicSharedMemorySize, SMEM_GEMM);
    cudaFuncSetAttribute(k_gemm_fc2,  cudaFuncAttributeMaxDynamicSharedMemorySize, SMEM_GEMM);
    cudaFuncSetAttribute(k_attn,      cudaFuncAttributeMaxDynamicSharedMemorySize, SMEM_ATTN);

    {
        int n0 = QKVW * Cc / 4, n1 = Cc * DH / 4, n2 = HID * Cc / 4, n3 = Cc * HID / 4;
        int tot = n0 + n1 + n2 + n3;
        k_half_all<<<(tot + 255) / 256, 256>>>((const float4*)qkv_w, n0,
                                               (const float4*)proj_w, n1,
                                               (const float4*)fc1_w, n2,
                                               (const float4*)fc2_w, n3);
    }
    {
        int tot = HEADS * Nt * Nt;
        k_bias_expand<<<(tot + 255) / 256, 256>>>(attn_bia, bias_idx, n_off);
    }
    k_win_ln<<<M_ATT / 8, 256>>>(x, ln_aw, ln_ab);
    k_gemm_qkv<<<dim3(QKVW / 128, (M_ATT + 127) / 128), 512, SMEM_GEMM>>>(qkv_b);
    k_attn<<<NW * HEADS, 256, SMEM_ATTN>>>();
    k_gemm_proj<<<dim3(Cc / 128, (M_ATT + 127) / 128), 512, SMEM_GEMM>>>(proj_b, x);
    k_conv_bn_ln<<<B_ * L_, 96>>>(conv_w, bn_w, bn_b, bn_m, bn_v, ln_mw, ln_mb);
    k_gemm_fc1<<<dim3(HID / 128, M_MLP / 128), 512, SMEM_GEMM>>>(fc1_b);
    k_gemm_fc2<<<dim3(Cc / 128, M_MLP / 128), 512, SMEM_GEMM>>>(fc2_b, out);
}

// round 15
// speedup vs baseline: 1.0943x; 1.0217x over previous
#include <cuda_runtime.h>
#include <cuda_fp16.h>
#include <math.h>
#include <stdint.h>

// ---------------- problem constants ----------------
#define B_      8
#define Hh      64
#define Ww      64
#define Cc      384
#define HEADS   12
#define WSs     14
#define KD      32
#define Nt      196
#define NW      200
#define L_      4096
#define M_MLP   32768
#define HID     1536
#define DH      384
#define QKVW    1152
#define SCALE_F 0.17677669529663687f
#define EPS_F   1e-5f

// attention tiling
#define NTP        208
#define AQ_STR     40
#define SMEM_ATTN  (3 * NTP * AQ_STR * 2)

// fp16 gemm smem: 3 stages x (A[128][40] + B[128][40]) halfs
#define GST_BYTES   20480
#define SMEM_GEMM   (3 * GST_BYTES)

// ---------------- scratch ----------------
__device__ __align__(16) __half g_xn[M_MLP * Cc];
__device__ __align__(16) __half g_qkv[(size_t)M_MLP * QKVW];   // pixel order
__device__ __align__(16) __half g_qkvc[QKVW];                  // padded-token const row
__device__ __align__(16) __half g_attno[M_MLP * Cc];           // pixel order
__device__ float  g_x1[M_MLP * Cc];
__device__ float  g_x2[M_MLP * Cc];
__device__ __align__(16) __half g_h1[(size_t)M_MLP * HID];
__device__ float  g_bias[HEADS * Nt * Nt];
__device__ __align__(16) __half g_wq[QKVW * Cc];
__device__ __align__(16) __half g_wp[Cc * DH];
__device__ __align__(16) __half g_w1[HID * Cc];
__device__ __align__(16) __half g_w2[Cc * HID];

// ---------------- helpers ----------------
__device__ __forceinline__ void mma_f16(float* c, const uint32_t* a, const uint32_t* b) {
    asm volatile(
        "mma.sync.aligned.m16n8k16.row.col.f32.f16.f16.f32 "
        "{%0,%1,%2,%3}, {%4,%5,%6,%7}, {%8,%9}, {%0,%1,%2,%3};\n"
        : "+f"(c[0]), "+f"(c[1]), "+f"(c[2]), "+f"(c[3])
        : "r"(a[0]), "r"(a[1]), "r"(a[2]), "r"(a[3]), "r"(b[0]), "r"(b[1]));
}

__device__ __forceinline__ void ldsm_x4(uint32_t* r, uint32_t saddr) {
    asm volatile("ldmatrix.sync.aligned.m8n8.x4.shared.b16 {%0,%1,%2,%3}, [%4];"
                 : "=r"(r[0]), "=r"(r[1]), "=r"(r[2]), "=r"(r[3]) : "r"(saddr));
}

__device__ __forceinline__ void ldsm_x4_t(uint32_t* r, uint32_t saddr) {
    asm volatile("ldmatrix.sync.aligned.m8n8.x4.trans.shared.b16 {%0,%1,%2,%3}, [%4];"
                 : "=r"(r[0]), "=r"(r[1]), "=r"(r[2]), "=r"(r[3]) : "r"(saddr));
}

__device__ __forceinline__ void cp_async16(uint32_t saddr, const void* gptr, int srcbytes) {
    asm volatile("cp.async.cg.shared.global [%0], [%1], 16, %2;\n"
                 :: "r"(saddr), "l"(gptr), "r"(srcbytes));
}

__device__ __forceinline__ uint32_t smem_u32(const void* p) {
    uint32_t a;
    asm("{ .reg .u64 t; cvta.to.shared.u64 t, %1; cvt.u32.u64 %0, t; }" : "=r"(a) : "l"(p));
    return a;
}

__device__ __forceinline__ uint32_t h2u(__half2 h) {
    return *(uint32_t*)&h;
}

// ---------------- weight conversion fp32 -> fp16 ----------------
__global__ void k_half_all(const float4* __restrict__ s0, int n0,
                           const float4* __restrict__ s1, int n1,
                           const float4* __restrict__ s2, int n2,
                           const float4* __restrict__ s3, int n3) {
    int i = blockIdx.x * blockDim.x + threadIdx.x;
    const float4* src; __half* dst; int j = i;
    if (j < n0) { src = s0; dst = g_wq; }
    else if ((j -= n0) < n1) { src = s1; dst = g_wp; }
    else if ((j -= n1) < n2) { src = s2; dst = g_w1; }
    else if ((j -= n2) < n3) { src = s3; dst = g_w2; }
    else return;
    float4 v = src[j];
    __half2* d2 = (__half2*)(dst + 4 * (size_t)j);
    d2[0] = __floats2half2_rn(v.x, v.y);
    d2[1] = __floats2half2_rn(v.z, v.w);
}

// ---------------- constant qkv row for padded tokens ----------------
// padded token input = LN(0) = beta  ->  qkv row = W @ fp16(beta) + bias
__global__ void k_qkv_const(const float* __restrict__ lnb,
                            const float* __restrict__ qkvb) {
    int j = blockIdx.x * blockDim.x + threadIdx.x;
    if (j >= QKVW) return;
    float acc = qkvb[j];
    const __half* wr = g_wq + (size_t)j * Cc;
    for (int k = 0; k < Cc; k++)
        acc += __half2float(wr[k]) * __half2float(__float2half(lnb[k]));
    float sc = ((j % 96) < 32) ? SCALE_F : 1.f;
    g_qkvc[j] = __float2half(acc * sc);
}

// ---------------- kernel: expand bias table ----------------
__global__ void k_bias_expand(const float* __restrict__ ab,
                              const int* __restrict__ bidx, int n_off) {
    int i = blockIdx.x * blockDim.x + threadIdx.x;
    if (i >= HEADS * Nt * Nt) return;
    int h  = i / (Nt * Nt);
    int ij = i - h * (Nt * Nt);
    g_bias[i] = ab[h * n_off + bidx[ij]];
}

// ---------------- kernel: plain LayerNorm over x (pixel order, fp16 out) --
__global__ void k_ln_x(const float* __restrict__ x,
                       const float* __restrict__ w,
                       const float* __restrict__ b) {
    int row = (blockIdx.x * blockDim.x + threadIdx.x) >> 5;
    int lane = threadIdx.x & 31;
    if (row >= M_MLP) return;
    const float* src = x + (size_t)row * Cc;
    float vals[12];
    float s = 0.f, s2 = 0.f;
#pragma unroll
    for (int i = 0; i < 12; i++) {
        float v = src[lane + i * 32];
        vals[i] = v; s += v; s2 += v * v;
    }
#pragma unroll
    for (int o = 16; o > 0; o >>= 1) {
        s  += __shfl_xor_sync(0xffffffffu, s,  o);
        s2 += __shfl_xor_sync(0xffffffffu, s2, o);
    }
    float mean = s * (1.f / Cc);
    float var  = s2 * (1.f / Cc) - mean * mean;
    float rstd = rsqrtf(var + EPS_F);
    __half* dst = g_xn + (size_t)row * Cc;
#pragma unroll
    for (int i = 0; i < 12; i++) {
        int c = lane + i * 32;
        dst[c] = __float2half((vals[i] - mean) * rstd * w[c] + b[c]);
    }
}

// ---------------- fused depthwise conv3x3 + BN + MLP LayerNorm ------------
__global__ __launch_bounds__(96) void k_conv_bn_ln(
    const float* __restrict__ cw,
    const float* __restrict__ bnw, const float* __restrict__ bnb,
    const float* __restrict__ bnm, const float* __restrict__ bnv,
    const float* __restrict__ lnw, const float* __restrict__ lnb) {
    __shared__ float sms[3], sms2[3];
    const int p = blockIdx.x;
    const int b = p >> 12, yx = p & 4095;
    const int y = yx >> 6, x = yx & 63;
    const int tid = threadIdx.x, lane = tid & 31, wid = tid >> 5;
    const int c0 = tid * 4;

    float4 acc = make_float4(0.f, 0.f, 0.f, 0.f);
#pragma unroll
    for (int ky = 0; ky < 3; ky++) {
        int yy = y + ky - 1;
        if (yy < 0 || yy >= Hh) continue;
#pragma unroll
        for (int kx = 0; kx < 3; kx++) {
            int xx = x + kx - 1;
            if (xx < 0 || xx >= Ww) continue;
            float4 in = *(const float4*)&g_x1[((size_t)b * L_ + (size_t)yy * Ww + xx) * Cc + c0];
            int wo = ky * 3 + kx;
            acc.x += in.x * cw[(c0 + 0) * 9 + wo];
            acc.y += in.y * cw[(c0 + 1) * 9 + wo];
            acc.z += in.z * cw[(c0 + 2) * 9 + wo];
            acc.w += in.w * cw[(c0 + 3) * 9 + wo];
        }
    }
    float4 o;
    o.x = (acc.x - bnm[c0 + 0]) * (rsqrtf(bnv[c0 + 0] + 1e-5f) * bnw[c0 + 0]) + bnb[c0 + 0];
    o.y = (acc.y - bnm[c0 + 1]) * (rsqrtf(bnv[c0 + 1] + 1e-5f) * bnw[c0 + 1]) + bnb[c0 + 1];
    o.z = (acc.z - bnm[c0 + 2]) * (rsqrtf(bnv[c0 + 2] + 1e-5f) * bnw[c0 + 2]) + bnb[c0 + 2];
    o.w = (acc.w - bnm[c0 + 3]) * (rsqrtf(bnv[c0 + 3] + 1e-5f) * bnw[c0 + 3]) + bnb[c0 + 3];
    *(float4*)&g_x2[(size_t)p * Cc + c0] = o;

    float s  = o.x + o.y + o.z + o.w;
    float s2 = o.x * o.x + o.y * o.y + o.z * o.z + o.w * o.w;
#pragma unroll
    for (int off = 16; off > 0; off >>= 1) {
        s  += __shfl_xor_sync(0xffffffffu, s,  off);
        s2 += __shfl_xor_sync(0xffffffffu, s2, off);
    }
    if (lane == 0) { sms[wid] = s; sms2[wid] = s2; }
    __syncthreads();
    float ts  = sms[0]  + sms[1]  + sms[2];
    float ts2 = sms2[0] + sms2[1] + sms2[2];
    float mean = ts * (1.f / Cc);
    float var  = ts2 * (1.f / Cc) - mean * mean;
    float rstd = rsqrtf(var + EPS_F);

    __half2* dst = (__half2*)(g_xn + (size_t)p * Cc + c0);
    dst[0] = __floats2half2_rn((o.x - mean) * rstd * lnw[c0 + 0] + lnb[c0 + 0],
                               (o.y - mean) * rstd * lnw[c0 + 1] + lnb[c0 + 1]);
    dst[1] = __floats2half2_rn((o.z - mean) * rstd * lnw[c0 + 2] + lnb[c0 + 2],
                               (o.w - mean) * rstd * lnw[c0 + 3] + lnb[c0 + 3]);
}

// ---------------- fp16 GEMM: 512 thr, 16 warps (4x4), 32x32 warp tiles -----
// EPI: 0 = qkv fp16 out with q-scale, 1 = GELU fp16 out, 3 = residual add
template <int EPI, int M, int Nn, int K>
__device__ __forceinline__ void gemm_f16_body(const __half* __restrict__ A,
                                              const __half* __restrict__ Bw,
                                              const float* __restrict__ bias,
                                              float* __restrict__ Cout,
                                              const float* __restrict__ res) {
    extern __shared__ __align__(16) char smraw[];
    const int tid = threadIdx.x, lane = tid & 31, wid = tid >> 5;
    const int g = lane >> 2, tig = lane & 3;
    const int warp_m = wid >> 2, warp_n = wid & 3;
    const int bm = blockIdx.y * 128, bn = blockIdx.x * 128;
    const int arow = tid >> 2, seg = tid & 3;

    const __half* a0b = A  + (size_t)(bm + arow) * K + seg * 8;
    const __half* b0b = Bw + (size_t)(bn + arow) * K + seg * 8;
    const uint32_t smb = smem_u32(smraw);
    const uint32_t sa0 = smb + arow * 80 + seg * 16;
    const uint32_t sb0 = sa0 + 10240;

    const int a_row = (lane & 15), a_k = 8 * (lane >> 4);
    const int b_row = (lane >> 4) * 8 + (lane & 7), b_k = 8 * ((lane >> 3) & 1);
    const uint32_t aA = smb + ((warp_m * 32 + a_row) * 40 + a_k) * 2;
    const uint32_t aB = smb + 10240 + ((warp_n * 32 + b_row) * 40 + b_k) * 2;

    const int KT = K / 32;
    auto load_stage = [&](int s, int kt) {
        int kc = kt * 32;
        uint32_t so = (uint32_t)(s * GST_BYTES);
        cp_async16(sa0 + so, a0b + kc, 16);
        cp_async16(sb0 + so, b0b + kc, 16);
        asm volatile("cp.async.commit_group;\n");
    };

    float acc[2][4][4];
#pragma unroll
    for (int mt = 0; mt < 2; mt++)
#pragma unroll
        for (int nt = 0; nt < 4; nt++)
#pragma unroll
            for (int r = 0; r < 4; r++) acc[mt][nt][r] = 0.f;

    load_stage(0, 0);
    load_stage(1, 1);

    for (int kt = 0; kt < KT; kt++) {
        if (kt + 1 < KT) {
            asm volatile("cp.async.wait_group 1;\n");
        } else {
            asm volatile("cp.async.wait_group 0;\n");
        }
        __syncthreads();
        if (kt + 2 < KT) load_stage((kt + 2) % 3, kt + 2);

        const uint32_t st = (uint32_t)((kt % 3) * GST_BYTES);
#pragma unroll
        for (int ks = 0; ks < 2; ks++) {
            const int kb = ks * 16;
            uint32_t afr[2][4], bfr2[2][4];
            ldsm_x4(afr[0], aA + st + kb * 2);
            ldsm_x4(afr[1], aA + st + (16 * 40 + kb) * 2);
            ldsm_x4(bfr2[0], aB + st + kb * 2);
            ldsm_x4(bfr2[1], aB + st + (16 * 40 + kb) * 2);
#pragma unroll
            for (int mt = 0; mt < 2; mt++) {
                mma_f16(acc[mt][0], afr[mt], &bfr2[0][0]);
                mma_f16(acc[mt][1], afr[mt], &bfr2[0][2]);
                mma_f16(acc[mt][2], afr[mt], &bfr2[1][0]);
                mma_f16(acc[mt][3], afr[mt], &bfr2[1][2]);
            }
        }
    }

    // ---------- vectorized epilogue ----------
#pragma unroll
    for (int mt = 0; mt < 2; mt++) {
        const int m0 = bm + warp_m * 32 + mt * 16 + g;
        const int m1 = m0 + 8;
#pragma unroll
        for (int nt = 0; nt < 4; nt++) {
            const int nn = bn + warp_n * 32 + nt * 8 + tig * 2;
            const float2 bv = *(const float2*)&bias[nn];
            float p00 = acc[mt][nt][0] + bv.x, p01 = acc[mt][nt][1] + bv.y;
            float p10 = acc[mt][nt][2] + bv.x, p11 = acc[mt][nt][3] + bv.y;
            if (EPI == 0) {
                const float sc = ((nn % 96) < 32) ? SCALE_F : 1.f;
                *(__half2*)((__half*)Cout + (size_t)m0 * Nn + nn) =
                    __floats2half2_rn(p00 * sc, p01 * sc);
                *(__half2*)((__half*)Cout + (size_t)m1 * Nn + nn) =
                    __floats2half2_rn(p10 * sc, p11 * sc);
            } else if (EPI == 1) {
                float g00 = 0.5f * p00 * (1.f + erff(p00 * 0.70710678118654752f));
                float g01 = 0.5f * p01 * (1.f + erff(p01 * 0.70710678118654752f));
                float g10 = 0.5f * p10 * (1.f + erff(p10 * 0.70710678118654752f));
                float g11 = 0.5f * p11 * (1.f + erff(p11 * 0.70710678118654752f));
                *(__half2*)((__half*)Cout + (size_t)m0 * Nn + nn) =
                    __floats2half2_rn(g00, g01);
                *(__half2*)((__half*)Cout + (size_t)m1 * Nn + nn) =
                    __floats2half2_rn(g10, g11);
            } else {
                size_t o0 = (size_t)m0 * Nn + nn;
                float2 r0 = *(const float2*)&res[o0];
                *(float2*)&Cout[o0] = make_float2(p00 + r0.x, p01 + r0.y);
                size_t o1 = (size_t)m1 * Nn + nn;
                float2 r1 = *(const float2*)&res[o1];
                *(float2*)&Cout[o1] = make_float2(p10 + r1.x, p11 + r1.y);
            }
        }
    }
}

__global__ __launch_bounds__(512, 2) void k_gemm_qkv(const float* __restrict__ b) {
    gemm_f16_body<0, M_MLP, QKVW, Cc>(g_xn, g_wq, b, (float*)g_qkv, nullptr);
}
__global__ __launch_bounds__(512, 2) void k_gemm_proj(const float* __restrict__ b,
                                                      const float* __restrict__ x) {
    gemm_f16_body<3, M_MLP, Cc, DH>(g_attno, g_wp, b, g_x1, x);
}
__global__ __launch_bounds__(512, 2) void k_gemm_fc1(const float* __restrict__ b) {
    gemm_f16_body<1, M_MLP, HID, Cc>(g_xn, g_w1, b, (float*)g_h1, nullptr);
}
__global__ __launch_bounds__(512, 2) void k_gemm_fc2(const float* __restrict__ b,
                                                     float* __restrict__ out) {
    gemm_f16_body<3, M_MLP, Cc, HID>(g_h1, g_w2, b, out, g_x2);
}

// ---------------- attention chunk step (online softmax) ----------------
template <int NTILES>
__device__ __forceinline__ void attn_chunk(
    int colbase, uint32_t smb, const uint32_t (&aq)[2][4],
    const float* __restrict__ bias_h, int row0, int row1, bool r0v, bool r1v,
    int lane, uint32_t vaddr0,
    float& m0, float& m1, float& l0, float& l1, float (&oacc)[4][4])
{
    const int tig = lane & 3;
    const int b_row = (lane >> 4) * 8 + (lane & 7), b_k = 8 * ((lane >> 3) & 1);

    float acc[NTILES][4];
#pragma unroll
    for (int np = 0; np < NTILES / 2; np++) {
        uint32_t ka = smb + (uint32_t)(NTP * AQ_STR * 2) +
                      ((colbase + np * 16 + b_row) * AQ_STR + b_k) * 2;
        uint32_t bf0[4], bf1[4];
        ldsm_x4(bf0, ka);
        ldsm_x4(bf1, ka + 32);
        float* a0 = acc[2 * np];
        float* a1 = acc[2 * np + 1];
        a0[0] = a0[1] = a0[2] = a0[3] = 0.f;
        a1[0] = a1[1] = a1[2] = a1[3] = 0.f;
        mma_f16(a0, aq[0], &bf0[0]);
        mma_f16(a0, aq[1], &bf1[0]);
        mma_f16(a1, aq[0], &bf0[2]);
        mma_f16(a1, aq[1], &bf1[2]);
    }

    float cm0 = -1e30f, cm1 = -1e30f;
#pragma unroll
    for (int nt = 0; nt < NTILES; nt++) {
        int col = colbase + nt * 8 + tig * 2;
        bool cv = col < Nt;
        float2 b0 = (cv && r0v) ? *(const float2*)(bias_h + (size_t)row0 * Nt + col)
                                : make_float2(0.f, 0.f);
        float2 b1 = (cv && r1v) ? *(const float2*)(bias_h + (size_t)row1 * Nt + col)
                                : make_float2(0.f, 0.f);
        acc[nt][0] = cv ? acc[nt][0] + b0.x : -1e30f;
        acc[nt][1] = cv ? acc[nt][1] + b0.y : -1e30f;
        acc[nt][2] = cv ? acc[nt][2] + b1.x : -1e30f;
        acc[nt][3] = cv ? acc[nt][3] + b1.y : -1e30f;
        cm0 = fmaxf(cm0, fmaxf(acc[nt][0], acc[nt][1]));
        cm1 = fmaxf(cm1, fmaxf(acc[nt][2], acc[nt][3]));
    }
    cm0 = fmaxf(cm0, __shfl_xor_sync(0xffffffffu, cm0, 1));
    cm0 = fmaxf(cm0, __shfl_xor_sync(0xffffffffu, cm0, 2));
    cm1 = fmaxf(cm1, __shfl_xor_sync(0xffffffffu, cm1, 1));
    cm1 = fmaxf(cm1, __shfl_xor_sync(0xffffffffu, cm1, 2));

    float mn0 = fmaxf(m0, cm0), mn1 = fmaxf(m1, cm1);
    float c0 = __expf(m0 - mn0), c1 = __expf(m1 - mn1);

    float s0 = 0.f, s1 = 0.f;
#pragma unroll
    for (int nt = 0; nt < NTILES; nt++) {
        acc[nt][0] = __expf(acc[nt][0] - mn0); s0 += acc[nt][0];
        acc[nt][1] = __expf(acc[nt][1] - mn0); s0 += acc[nt][1];
        acc[nt][2] = __expf(acc[nt][2] - mn1); s1 += acc[nt][2];
        acc[nt][3] = __expf(acc[nt][3] - mn1); s1 += acc[nt][3];
    }
    s0 += __shfl_xor_sync(0xffffffffu, s0, 1);
    s0 += __shfl_xor_sync(0xffffffffu, s0, 2);
    s1 += __shfl_xor_sync(0xffffffffu, s1, 1);
    s1 += __shfl_xor_sync(0xffffffffu, s1, 2);
    l0 = l0 * c0 + s0;
    l1 = l1 * c1 + s1;
    m0 = mn0; m1 = mn1;

#pragma unroll
    for (int nt = 0; nt < 4; nt++) {
        oacc[nt][0] *= c0; oacc[nt][1] *= c0;
        oacc[nt][2] *= c1; oacc[nt][3] *= c1;
    }

#pragma unroll
    for (int kk = 0; kk < NTILES / 2; kk++) {
        uint32_t pa[4];
        pa[0] = h2u(__floats2half2_rn(acc[2*kk  ][0], acc[2*kk  ][1]));
        pa[1] = h2u(__floats2half2_rn(acc[2*kk  ][2], acc[2*kk  ][3]));
        pa[2] = h2u(__floats2half2_rn(acc[2*kk+1][0], acc[2*kk+1][1]));
        pa[3] = h2u(__floats2half2_rn(acc[2*kk+1][2], acc[2*kk+1][3]));
        uint32_t vb0[4], vb1[4];
        uint32_t va = vaddr0 + (uint32_t)((colbase + kk * 16) * AQ_STR * 2);
        ldsm_x4_t(vb0, va);
        ldsm_x4_t(vb1, va + 32);
        mma_f16(oacc[0], pa, &vb0[0]);
        mma_f16(oacc[1], pa, &vb0[2]);
        mma_f16(oacc[2], pa, &vb1[0]);
        mma_f16(oacc[3], pa, &vb1[2]);
    }
}

// ---------------- fp16 attention: pixel-order gather/scatter --------------
__global__ __launch_bounds__(256, 2) void k_attn() {
    extern __shared__ __align__(16) __half smh[];
    __half* qs = smh;
    __half* ks = smh + NTP * AQ_STR;
    __half* vs = smh + 2 * NTP * AQ_STR;

    const int blk = blockIdx.x;
    const int w = blk / HEADS, h = blk - w * HEADS;
    const int bb = w / 25, rem = w - bb * 25;
    const int wy = rem / 5, wx = rem - wy * 5;
    const int tid = threadIdx.x, lane = tid & 31, wid = tid >> 5;
    const int g = lane >> 2, tig = lane & 3;
    const uint32_t smb = smem_u32(smh);

    // stage: gather q/k/v per token (valid pixel or const padded row)
    for (int idx = tid; idx < NTP * 4; idx += 256) {
        int r = idx >> 2, d8 = (idx & 3) * 8;
        uint4 q4, k4, v4;
        if (r < Nt) {
            int ty = r / WSs, tx = r - ty * WSs;
            int gy = wy * WSs + ty, gx = wx * WSs + tx;
            const __half* rp;
            if (gy < Hh && gx < Ww)
                rp = g_qkv + ((size_t)(bb * L_ + gy * Ww + gx)) * QKVW + h * 96;
            else
                rp = g_qkvc + h * 96;
            q4 = *(const uint4*)(rp + d8);
            k4 = *(const uint4*)(rp + 32 + d8);
            v4 = *(const uint4*)(rp + 64 + d8);
        } else {
            q4 = k4 = v4 = make_uint4(0, 0, 0, 0);
        }
        *(uint4*)(qs + r * AQ_STR + d8) = q4;
        *(uint4*)(ks + r * AQ_STR + d8) = k4;
        *(uint4*)(vs + r * AQ_STR + d8) = v4;
    }
    __syncthreads();

    const float* bias_h = g_bias + (size_t)h * Nt * Nt;

    const int a_row = (lane & 15), a_k = 8 * (lane >> 4);
    const uint32_t vs_off = (uint32_t)(2 * NTP * AQ_STR * 2);
    const uint32_t vaddr0 = smb + vs_off + (((lane & 15)) * AQ_STR + 8 * (lane >> 4)) * 2;

    for (int tt = wid; tt < 13; tt += 8) {
        const int row0 = tt * 16 + g, row1 = row0 + 8;
        const bool r0v = row0 < Nt, r1v = row1 < Nt;

        uint32_t aq[2][4];
        {
            uint32_t qa = smb + ((tt * 16 + a_row) * AQ_STR + a_k) * 2;
            ldsm_x4(aq[0], qa);
            ldsm_x4(aq[1], qa + 32);
        }

        float m0 = -1e30f, m1 = -1e30f, l0 = 0.f, l1 = 0.f;
        float oacc[4][4];
#pragma unroll
        for (int nt = 0; nt < 4; nt++)
            oacc[nt][0] = oacc[nt][1] = oacc[nt][2] = oacc[nt][3] = 0.f;

        attn_chunk<14>(0,   smb, aq, bias_h, row0, row1, r0v, r1v, lane, vaddr0,
                       m0, m1, l0, l1, oacc);
        attn_chunk<12>(112, smb, aq, bias_h, row0, row1, r0v, r1v, lane, vaddr0,
                       m0, m1, l0, l1, oacc);

        const float inv0 = 1.f / l0, inv1 = 1.f / l1;
        if (r0v) {
            int ty = row0 / WSs, tx = row0 - ty * WSs;
            int gy = wy * WSs + ty, gx = wx * WSs + tx;
            if (gy < Hh && gx < Ww) {
                __half* op = g_attno + ((size_t)(bb * L_ + gy * Ww + gx)) * DH + h * KD;
#pragma unroll
                for (int nt = 0; nt < 4; nt++)
                    *(__half2*)(op + nt * 8 + tig * 2) =
                        __floats2half2_rn(oacc[nt][0] * inv0, oacc[nt][1] * inv0);
            }
        }
        if (r1v) {
            int ty = row1 / WSs, tx = row1 - ty * WSs;
            int gy = wy * WSs + ty, gx = wx * WSs + tx;
            if (gy < Hh && gx < Ww) {
                __half* op = g_attno + ((size_t)(bb * L_ + gy * Ww + gx)) * DH + h * KD;
#pragma unroll
                for (int nt = 0; nt < 4; nt++)
                    *(__half2*)(op + nt * 8 + tig * 2) =
                        __floats2half2_rn(oacc[nt][2] * inv1, oacc[nt][3] * inv1);
            }
        }
    }
}

// ---------------- launcher ----------------
extern "C" void kernel_launch(void* const* d_in, const int* in_sizes, int n_in,
                              void* d_out, int out_size) {
    const float* x        = (const float*)d_in[0];
    const float* ln_aw    = (const float*)d_in[1];
    const float* ln_ab    = (const float*)d_in[2];
    const float* qkv_w    = (const float*)d_in[3];
    const float* qkv_b    = (const float*)d_in[4];
    const float* proj_w   = (const float*)d_in[5];
    const float* proj_b   = (const float*)d_in[6];
    const float* attn_bia = (const float*)d_in[7];
    const float* conv_w   = (const float*)d_in[8];
    const float* bn_w     = (const float*)d_in[9];
    const float* bn_b     = (const float*)d_in[10];
    const float* bn_m     = (const float*)d_in[11];
    const float* bn_v     = (const float*)d_in[12];
    const float* ln_mw    = (const float*)d_in[13];
    const float* ln_mb    = (const float*)d_in[14];
    const float* fc1_w    = (const float*)d_in[15];
    const float* fc1_b    = (const float*)d_in[16];
    const float* fc2_w    = (const float*)d_in[17];
    const float* fc2_b    = (const float*)d_in[18];
    const int*   bias_idx = (const int*)d_in[19];
    float* out = (float*)d_out;

    int n_off = in_sizes[7] / HEADS;

    cudaFuncSetAttribute(k_gemm_qkv,  cudaFuncAttributeMaxDynamicSharedMemorySize, SMEM_GEMM);
    cudaFuncSetAttribute(k_gemm_proj, cudaFuncAttributeMaxDynamicSharedMemorySize, SMEM_GEMM);
    cudaFuncSetAttribute(k_gemm_fc1,  cudaFuncAttributeMaxDynamicSharedMemorySize, SMEM_GEMM);
    cudaFuncSetAttribute(k_gemm_fc2,  cudaFuncAttributeMaxDynamicSharedMemorySize, SMEM_GEMM);
    cudaFuncSetAttribute(k_attn,      cudaFuncAttributeMaxDynamicSharedMemorySize, SMEM_ATTN);

    {
        int n0 = QKVW * Cc / 4, n1 = Cc * DH / 4, n2 = HID * Cc / 4, n3 = Cc * HID / 4;
        int tot = n0 + n1 + n2 + n3;
        k_half_all<<<(tot + 255) / 256, 256>>>((const float4*)qkv_w, n0,
                                               (const float4*)proj_w, n1,
                                               (const float4*)fc1_w, n2,
                                               (const float4*)fc2_w, n3);
    }
    {
        int tot = HEADS * Nt * Nt;
        k_bias_expand<<<(tot + 255) / 256, 256>>>(attn_bia, bias_idx, n_off);
    }
    k_qkv_const<<<(QKVW + 127) / 128, 128>>>(ln_ab, qkv_b);
    k_ln_x<<<M_MLP / 8, 256>>>(x, ln_aw, ln_ab);
    k_gemm_qkv<<<dim3(QKVW / 128, M_MLP / 128), 512, SMEM_GEMM>>>(qkv_b);
    k_attn<<<NW * HEADS, 256, SMEM_ATTN>>>();
    k_gemm_proj<<<dim3(Cc / 128, M_MLP / 128), 512, SMEM_GEMM>>>(proj_b, x);
    k_conv_bn_ln<<<B_ * L_, 96>>>(conv_w, bn_w, bn_b, bn_m, bn_v, ln_mw, ln_mb);
    k_gemm_fc1<<<dim3(HID / 128, M_MLP / 128), 512, SMEM_GEMM>>>(fc1_b);
    k_gemm_fc2<<<dim3(Cc / 128, M_MLP / 128), 512, SMEM_GEMM>>>(fc2_b, out);
}